// round 4
// baseline (speedup 1.0000x reference)
#include <cuda_runtime.h>
#include <math.h>

#define N_NODES 50000
#define N_EDGES 800000
#define N_TOT   (N_EDGES + N_NODES)   // edges + self loops
#define IN_DIM  128
#define HIDDEN  64
#define NEG_SLOPE 0.2f

// ---------------- scratch (__device__ globals; no allocations) ----------------
__device__ __align__(16) float g_h[N_NODES * HIDDEN];      // h [N, 64]
__device__ float  g_asrc[N_NODES];
__device__ float  g_adst[N_NODES];
__device__ __align__(16) int g_cnt[N_NODES];
__device__ __align__(16) int g_row_start[N_NODES + 4];
__device__ __align__(16) int g_cursor[N_NODES];
__device__ __align__(16) long long g_csr[N_TOT];   // packed: lo=src, hi=exp(e) bits
__device__ int    g_is64;

// ---------------- packed fp32x2 helpers ----------------
__device__ __forceinline__ void ffma2(unsigned long long& acc,
                                      unsigned long long a,
                                      unsigned long long b) {
    asm("fma.rn.f32x2 %0, %1, %2, %0;" : "+l"(acc) : "l"(a), "l"(b));
}
__device__ __forceinline__ unsigned long long pack2(float lo, float hi) {
    unsigned long long r;
    asm("mov.b64 %0, {%1, %2};" : "=l"(r) : "f"(lo), "f"(hi));
    return r;
}
__device__ __forceinline__ void unpack2(unsigned long long v, float& lo, float& hi) {
    asm("mov.b64 {%0, %1}, %2;" : "=f"(lo), "=f"(hi) : "l"(v));
}

// ---------------- K0: init counts + dtype detect (parallel) ----------------
__global__ void k_init(const void* __restrict__ ei_raw) {
    int i = blockIdx.x * 256 + threadIdx.x;
    if (i < N_NODES) g_cnt[i] = 1;            // self loop contributes 1
    if (i == 0) g_row_start[N_NODES] = N_TOT; // constant total
    if (blockIdx.x == 0 && threadIdx.x < 32) {
        const long long* p = (const long long*)ei_raw;
        int bad = 0;
#pragma unroll
        for (int j = 0; j < 8; j++) {
            long long v = p[threadIdx.x * 8 + j];
            if (v < 0 || v >= N_NODES) bad = 1;
        }
        unsigned any = __ballot_sync(0xffffffffu, bad);
        if (threadIdx.x == 0) g_is64 = (any == 0u) ? 1 : 0;
    }
}

// ---------------- K1: h = x @ W^T (fp32x2 packed GEMM) + fused a_src/a_dst ----
#define GN 64   // nodes per block
__global__ __launch_bounds__(256) void k_gemm(const float* __restrict__ x,
                                              const float* __restrict__ W,
                                              const float* __restrict__ att_src,
                                              const float* __restrict__ att_dst) {
    __shared__ float Wt[IN_DIM][HIDDEN];   // 32KB, Wt[c][k]
    __shared__ float Xs[GN][64];           // 16KB, one 64-col chunk
    const int tid = threadIdx.x;
    const int n0  = blockIdx.x * GN;

    for (int i = tid; i < HIDDEN * IN_DIM; i += 256) {
        int k = i >> 7, c = i & 127;
        Wt[c][k] = W[i];
    }

    const int tx = tid & 15;   // k quad: k = tx*4 .. tx*4+3
    const int ty = tid >> 4;   // node group: nodes n0 + ty*4 .. +3
    unsigned long long acc[4][2];
#pragma unroll
    for (int n = 0; n < 4; n++) { acc[n][0] = 0ull; acc[n][1] = 0ull; }

    const float4* x4 = (const float4*)x;
    for (int kc = 0; kc < 2; kc++) {
        __syncthreads();
        for (int i = tid; i < GN * 16; i += 256) {
            int n = i >> 4, c4 = i & 15;
            int node = n0 + n;
            float4 v = (node < N_NODES) ? x4[(size_t)node * 32 + kc * 16 + c4]
                                        : make_float4(0.f, 0.f, 0.f, 0.f);
            ((float4*)Xs[n])[c4] = v;
        }
        __syncthreads();
#pragma unroll 8
        for (int c = 0; c < 64; c++) {
            ulonglong2 wp = *(const ulonglong2*)&Wt[kc * 64 + c][tx * 4];
#pragma unroll
            for (int n = 0; n < 4; n++) {
                float xv = Xs[ty * 4 + n][c];
                unsigned long long xx = pack2(xv, xv);
                ffma2(acc[n][0], xx, wp.x);
                ffma2(acc[n][1], xx, wp.y);
            }
        }
    }

    float4 as4 = ((const float4*)att_src)[tx];
    float4 ad4 = ((const float4*)att_dst)[tx];
#pragma unroll
    for (int n = 0; n < 4; n++) {
        float h0, h1, h2, h3;
        unpack2(acc[n][0], h0, h1);
        unpack2(acc[n][1], h2, h3);
        int node = n0 + ty * 4 + n;
        if (node < N_NODES) {
            *(float4*)&g_h[(size_t)node * HIDDEN + tx * 4] =
                make_float4(h0, h1, h2, h3);
        }
        float s1 = h0 * as4.x + h1 * as4.y + h2 * as4.z + h3 * as4.w;
        float s2 = h0 * ad4.x + h1 * ad4.y + h2 * ad4.z + h3 * ad4.w;
#pragma unroll
        for (int off = 8; off > 0; off >>= 1) {
            s1 += __shfl_xor_sync(0xffffffffu, s1, off);
            s2 += __shfl_xor_sync(0xffffffffu, s2, off);
        }
        if (tx == 0 && node < N_NODES) {
            g_asrc[node] = s1;
            g_adst[node] = s2;
        }
    }
}

// ---------------- K2: degree count (4 edges / thread) ----------------
__global__ void k_count(const void* __restrict__ ei) {
    int t = blockIdx.x * 256 + threadIdx.x;
    if (t >= N_EDGES / 4) return;
    if (g_is64) {
        const long long* p = (const long long*)ei + N_EDGES + (size_t)t * 4;
#pragma unroll
        for (int j = 0; j < 4; j++) atomicAdd(&g_cnt[(int)p[j]], 1);
    } else {
        int4 d = ((const int4*)ei)[N_EDGES / 4 + t];
        atomicAdd(&g_cnt[d.x], 1);
        atomicAdd(&g_cnt[d.y], 1);
        atomicAdd(&g_cnt[d.z], 1);
        atomicAdd(&g_cnt[d.w], 1);
    }
}

// ---------------- K3: latency-flat single-block scan ----------------
// Each thread owns 13 contiguous int4 (1024*13 = 13312 >= 12500).
// Pass A: independent loads (MLP=13) -> local sum. One block scan. Pass B: reload+write.
#define SC_N4 (N_NODES / 4)   // 12500
#define SC_C  13
__global__ __launch_bounds__(1024) void k_scan() {
    __shared__ int warp_off[32];
    const int tid  = threadIdx.x;
    const int lane = tid & 31;
    const int wid  = tid >> 5;
    const int4* cnt4 = (const int4*)g_cnt;

    int sum = 0;
#pragma unroll
    for (int j = 0; j < SC_C; j++) {
        int idx = tid * SC_C + j;
        if (idx < SC_N4) {
            int4 v = cnt4[idx];
            sum += v.x + v.y + v.z + v.w;
        }
    }
    // block exclusive scan of per-thread sums
    int incl = sum;
#pragma unroll
    for (int off = 1; off < 32; off <<= 1) {
        int t = __shfl_up_sync(0xffffffffu, incl, off);
        if (lane >= off) incl += t;
    }
    if (lane == 31) warp_off[wid] = incl;
    __syncthreads();
    if (tid < 32) {
        int ws = warp_off[tid];
        int wincl = ws;
#pragma unroll
        for (int off = 1; off < 32; off <<= 1) {
            int t = __shfl_up_sync(0xffffffffu, wincl, off);
            if (lane >= off) wincl += t;
        }
        warp_off[tid] = wincl - ws;
    }
    __syncthreads();
    int run = warp_off[wid] + incl - sum;   // exclusive prefix for this thread

#pragma unroll
    for (int j = 0; j < SC_C; j++) {
        int idx = tid * SC_C + j;
        if (idx < SC_N4) {
            int4 v = cnt4[idx];
            int e0 = run, e1 = e0 + v.x, e2 = e1 + v.y, e3 = e2 + v.z;
            int4 r = make_int4(e0, e1, e2, e3);
            ((int4*)g_row_start)[idx] = r;
            ((int4*)g_cursor)[idx]    = r;
            run = e3 + v.w;
        }
    }
}

// ---------------- K4: scatter edges + self loops (packed 8B, exp pre-applied) -
__device__ __forceinline__ long long pack_edge(int src, float ev) {
    return ((long long)__float_as_int(ev) << 32) | (unsigned)src;
}
__global__ void k_scatter(const void* __restrict__ ei) {
    int t = blockIdx.x * 256 + threadIdx.x;
    if (t < N_EDGES / 4) {
        int sx[4], dx[4];
        if (g_is64) {
            const long long* ps = (const long long*)ei + (size_t)t * 4;
            const long long* pd = ps + N_EDGES;
#pragma unroll
            for (int j = 0; j < 4; j++) { sx[j] = (int)ps[j]; dx[j] = (int)pd[j]; }
        } else {
            int4 s4 = ((const int4*)ei)[t];
            int4 d4 = ((const int4*)ei)[N_EDGES / 4 + t];
            sx[0] = s4.x; sx[1] = s4.y; sx[2] = s4.z; sx[3] = s4.w;
            dx[0] = d4.x; dx[1] = d4.y; dx[2] = d4.z; dx[3] = d4.w;
        }
#pragma unroll
        for (int j = 0; j < 4; j++) {
            float v = g_asrc[sx[j]] + g_adst[dx[j]];
            float lv = (v > 0.f) ? v : NEG_SLOPE * v;
            float ev = __expf(lv);
            int pos = atomicAdd(&g_cursor[dx[j]], 1);
            g_csr[pos] = pack_edge(sx[j], ev);
        }
    } else {
        int node = t - N_EDGES / 4;   // self loop
        if (node < N_NODES) {
            float v = g_asrc[node] + g_adst[node];
            float lv = (v > 0.f) ? v : NEG_SLOPE * v;
            float ev = __expf(lv);
            int pos = atomicAdd(&g_cursor[node], 1);
            g_csr[pos] = pack_edge(node, ev);
        }
    }
}

// ---------------- K5: fused aggregate + head (warp per node, no max pass) ----
__global__ __launch_bounds__(256) void k_agg(const float* __restrict__ bias,
                                             const float* __restrict__ wlin,
                                             const float* __restrict__ blin,
                                             float* __restrict__ y) {
    int node = blockIdx.x * 8 + (threadIdx.x >> 5);
    int lane = threadIdx.x & 31;
    if (node >= N_NODES) return;

    int beg = g_row_start[node];
    int end = g_row_start[node + 1];

    const float2* h2 = (const float2*)g_h;
    float2 acc = make_float2(0.f, 0.f);
    float s = 0.f;
    for (int base = beg; base < end; base += 32) {
        int i = base + lane;
        float ex = 0.f;
        int sid = 0;
        if (i < end) {
            long long p = g_csr[i];
            sid = (int)p;
            ex  = __int_as_float((int)(p >> 32));
        }
        s += ex;
        int cnt = min(32, end - base);
        for (int j = 0; j < cnt; j++) {
            float w = __shfl_sync(0xffffffffu, ex, j);
            int sj  = __shfl_sync(0xffffffffu, sid, j);
            float2 hv = h2[(size_t)sj * 32 + lane];
            acc.x += w * hv.x;
            acc.y += w * hv.y;
        }
    }
#pragma unroll
    for (int off = 16; off > 0; off >>= 1)
        s += __shfl_xor_sync(0xffffffffu, s, off);

    float inv = __frcp_rn(s);
    float o0 = fmaxf(acc.x * inv + bias[2 * lane], 0.f);
    float o1 = fmaxf(acc.y * inv + bias[2 * lane + 1], 0.f);
    float p = o0 * wlin[2 * lane] + o1 * wlin[2 * lane + 1];
#pragma unroll
    for (int off = 16; off > 0; off >>= 1)
        p += __shfl_xor_sync(0xffffffffu, p, off);
    if (lane == 0) {
        float t = p + blin[0];
        y[node] = __frcp_rn(1.f + __expf(-t));
    }
}

// ---------------- launch ----------------
extern "C" void kernel_launch(void* const* d_in, const int* in_sizes, int n_in,
                              void* d_out, int out_size) {
    const float* x       = (const float*)d_in[0];
    const void*  ei      = d_in[1];
    const float* W       = (const float*)d_in[2];
    const float* att_src = (const float*)d_in[3];
    const float* att_dst = (const float*)d_in[4];
    const float* bias    = (const float*)d_in[5];
    const float* wlin    = (const float*)d_in[6];
    const float* blin    = (const float*)d_in[7];
    float*       y       = (float*)d_out;

    k_init<<<(N_NODES + 255) / 256, 256>>>(ei);
    k_gemm<<<(N_NODES + GN - 1) / GN, 256>>>(x, W, att_src, att_dst);
    k_count<<<(N_EDGES / 4 + 255) / 256, 256>>>(ei);
    k_scan<<<1, 1024>>>();
    k_scatter<<<(N_EDGES / 4 + N_NODES + 255) / 256, 256>>>(ei);
    k_agg<<<(N_NODES + 7) / 8, 256>>>(bias, wlin, blin, y);
}

// round 5
// speedup vs baseline: 1.2501x; 1.2501x over previous
#include <cuda_runtime.h>
#include <math.h>

#define N_NODES 50000
#define N_EDGES 800000
#define N_TOT   (N_EDGES + N_NODES)   // edges + self loops
#define IN_DIM  128
#define HIDDEN  64
#define NEG_SLOPE 0.2f

// ---------------- scratch (__device__ globals; no allocations) ----------------
__device__ __align__(16) float g_h[N_NODES * HIDDEN];      // h [N, 64]
__device__ float  g_asrc[N_NODES];
__device__ float  g_adst[N_NODES];
__device__ __align__(16) int g_cnt[N_NODES];
__device__ __align__(16) int g_row_start[N_NODES + 4];
__device__ __align__(16) int g_cursor[N_NODES];
__device__ __align__(16) long long g_csr[N_TOT];   // packed: lo=src, hi=exp(e) bits
__device__ int    g_is64;

#define SC_N4     (N_NODES / 4)          // 12500 int4
#define SCAN_NBLK ((SC_N4 + 1023) / 1024) // 13
__device__ unsigned int g_blk_state[SCAN_NBLK];  // 0=empty, tag1=agg, tag2=prefix

// ---------------- packed fp32x2 helpers ----------------
__device__ __forceinline__ void ffma2(unsigned long long& acc,
                                      unsigned long long a,
                                      unsigned long long b) {
    asm("fma.rn.f32x2 %0, %1, %2, %0;" : "+l"(acc) : "l"(a), "l"(b));
}
__device__ __forceinline__ unsigned long long pack2(float lo, float hi) {
    unsigned long long r;
    asm("mov.b64 %0, {%1, %2};" : "=l"(r) : "f"(lo), "f"(hi));
    return r;
}
__device__ __forceinline__ void unpack2(unsigned long long v, float& lo, float& hi) {
    asm("mov.b64 {%0, %1}, %2;" : "=f"(lo), "=f"(hi) : "l"(v));
}

// ---------------- K0: init counts + scan states + dtype detect ----------------
__global__ void k_init(const void* __restrict__ ei_raw) {
    int i = blockIdx.x * 256 + threadIdx.x;
    if (i < N_NODES) g_cnt[i] = 1;            // self loop contributes 1
    if (i == 0) g_row_start[N_NODES] = N_TOT; // constant total
    if (i < SCAN_NBLK) g_blk_state[i] = 0u;
    if (blockIdx.x == 0 && threadIdx.x < 32) {
        const long long* p = (const long long*)ei_raw;
        int bad = 0;
#pragma unroll
        for (int j = 0; j < 8; j++) {
            long long v = p[threadIdx.x * 8 + j];
            if (v < 0 || v >= N_NODES) bad = 1;
        }
        unsigned any = __ballot_sync(0xffffffffu, bad);
        if (threadIdx.x == 0) g_is64 = (any == 0u) ? 1 : 0;
    }
}

// ---------------- K1: h = x @ W^T (fp32x2 packed GEMM) + fused a_src/a_dst ----
#define GN 64   // nodes per block
__global__ __launch_bounds__(256) void k_gemm(const float* __restrict__ x,
                                              const float* __restrict__ W,
                                              const float* __restrict__ att_src,
                                              const float* __restrict__ att_dst) {
    __shared__ float Wt[IN_DIM][HIDDEN];   // 32KB, Wt[c][k]
    __shared__ float Xs[GN][64];           // 16KB, one 64-col chunk
    const int tid = threadIdx.x;
    const int n0  = blockIdx.x * GN;

    for (int i = tid; i < HIDDEN * IN_DIM; i += 256) {
        int k = i >> 7, c = i & 127;
        Wt[c][k] = W[i];
    }

    const int tx = tid & 15;   // k quad
    const int ty = tid >> 4;   // node group
    unsigned long long acc[4][2];
#pragma unroll
    for (int n = 0; n < 4; n++) { acc[n][0] = 0ull; acc[n][1] = 0ull; }

    const float4* x4 = (const float4*)x;
    for (int kc = 0; kc < 2; kc++) {
        __syncthreads();
        for (int i = tid; i < GN * 16; i += 256) {
            int n = i >> 4, c4 = i & 15;
            int node = n0 + n;
            float4 v = (node < N_NODES) ? x4[(size_t)node * 32 + kc * 16 + c4]
                                        : make_float4(0.f, 0.f, 0.f, 0.f);
            ((float4*)Xs[n])[c4] = v;
        }
        __syncthreads();
#pragma unroll 8
        for (int c = 0; c < 64; c++) {
            ulonglong2 wp = *(const ulonglong2*)&Wt[kc * 64 + c][tx * 4];
#pragma unroll
            for (int n = 0; n < 4; n++) {
                float xv = Xs[ty * 4 + n][c];
                unsigned long long xx = pack2(xv, xv);
                ffma2(acc[n][0], xx, wp.x);
                ffma2(acc[n][1], xx, wp.y);
            }
        }
    }

    float4 as4 = ((const float4*)att_src)[tx];
    float4 ad4 = ((const float4*)att_dst)[tx];
#pragma unroll
    for (int n = 0; n < 4; n++) {
        float h0, h1, h2, h3;
        unpack2(acc[n][0], h0, h1);
        unpack2(acc[n][1], h2, h3);
        int node = n0 + ty * 4 + n;
        if (node < N_NODES) {
            *(float4*)&g_h[(size_t)node * HIDDEN + tx * 4] =
                make_float4(h0, h1, h2, h3);
        }
        float s1 = h0 * as4.x + h1 * as4.y + h2 * as4.z + h3 * as4.w;
        float s2 = h0 * ad4.x + h1 * ad4.y + h2 * ad4.z + h3 * ad4.w;
#pragma unroll
        for (int off = 8; off > 0; off >>= 1) {
            s1 += __shfl_xor_sync(0xffffffffu, s1, off);
            s2 += __shfl_xor_sync(0xffffffffu, s2, off);
        }
        if (tx == 0 && node < N_NODES) {
            g_asrc[node] = s1;
            g_adst[node] = s2;
        }
    }
}

// ---------------- K2: degree count (4 edges / thread) ----------------
__global__ void k_count(const void* __restrict__ ei) {
    int t = blockIdx.x * 256 + threadIdx.x;
    if (t >= N_EDGES / 4) return;
    if (g_is64) {
        const long long* p = (const long long*)ei + N_EDGES + (size_t)t * 4;
#pragma unroll
        for (int j = 0; j < 4; j++) atomicAdd(&g_cnt[(int)p[j]], 1);
    } else {
        int4 d = ((const int4*)ei)[N_EDGES / 4 + t];
        atomicAdd(&g_cnt[d.x], 1);
        atomicAdd(&g_cnt[d.y], 1);
        atomicAdd(&g_cnt[d.z], 1);
        atomicAdd(&g_cnt[d.w], 1);
    }
}

// ---------------- K3: multi-block decoupled-lookback scan ----------------
// 13 blocks x 1024 threads, one int4 per thread. Only the tagged state word
// crosses blocks (relaxed atomics suffice). Deterministic.
#define TAG_AGG (1u << 30)
#define TAG_PRE (2u << 30)
#define VAL_MSK ((1u << 30) - 1u)
__global__ __launch_bounds__(1024) void k_scan() {
    __shared__ int warp_sums[32];
    __shared__ int blk_total_sh;
    __shared__ int blk_off_sh;
    const int tid  = threadIdx.x;
    const int lane = tid & 31;
    const int wid  = tid >> 5;
    const int bid  = blockIdx.x;
    const int idx  = bid * 1024 + tid;

    int4 v = make_int4(0, 0, 0, 0);
    if (idx < SC_N4) v = ((const int4*)g_cnt)[idx];
    int s = v.x + v.y + v.z + v.w;

    int incl = s;
#pragma unroll
    for (int off = 1; off < 32; off <<= 1) {
        int t = __shfl_up_sync(0xffffffffu, incl, off);
        if (lane >= off) incl += t;
    }
    if (lane == 31) warp_sums[wid] = incl;
    __syncthreads();
    if (tid < 32) {
        int ws = warp_sums[tid];
        int wincl = ws;
#pragma unroll
        for (int off = 1; off < 32; off <<= 1) {
            int t = __shfl_up_sync(0xffffffffu, wincl, off);
            if (lane >= off) wincl += t;
        }
        warp_sums[tid] = wincl - ws;     // exclusive warp offsets
        if (tid == 31) blk_total_sh = wincl;
    }
    __syncthreads();
    int thread_excl = warp_sums[wid] + incl - s;

    if (tid == 0) {
        unsigned bt = (unsigned)blk_total_sh;
        int excl;
        if (bid == 0) {
            excl = 0;
            atomicExch(&g_blk_state[0], TAG_PRE | bt);
        } else {
            atomicExch(&g_blk_state[bid], TAG_AGG | bt);
            unsigned run = 0;
            int j = bid - 1;
            while (1) {
                unsigned st = atomicAdd(&g_blk_state[j], 0u);
                unsigned tag = st >> 30;
                if (tag == 2u) { run += st & VAL_MSK; break; }
                if (tag == 1u) { run += st & VAL_MSK; j--; }
            }
            excl = (int)run;
            atomicExch(&g_blk_state[bid], TAG_PRE | (run + bt));
        }
        blk_off_sh = excl;
    }
    __syncthreads();

    if (idx < SC_N4) {
        int e0 = blk_off_sh + thread_excl;
        int e1 = e0 + v.x, e2 = e1 + v.y, e3 = e2 + v.z;
        int4 r = make_int4(e0, e1, e2, e3);
        ((int4*)g_row_start)[idx] = r;
        ((int4*)g_cursor)[idx]    = r;
    }
}

// ---------------- K4: scatter edges + self loops (packed 8B, exp pre-applied) -
__device__ __forceinline__ long long pack_edge(int src, float ev) {
    return ((long long)__float_as_int(ev) << 32) | (unsigned)src;
}
__global__ void k_scatter(const void* __restrict__ ei) {
    int t = blockIdx.x * 256 + threadIdx.x;
    if (t < N_EDGES / 4) {
        int sx[4], dx[4];
        if (g_is64) {
            const long long* ps = (const long long*)ei + (size_t)t * 4;
            const long long* pd = ps + N_EDGES;
#pragma unroll
            for (int j = 0; j < 4; j++) { sx[j] = (int)ps[j]; dx[j] = (int)pd[j]; }
        } else {
            int4 s4 = ((const int4*)ei)[t];
            int4 d4 = ((const int4*)ei)[N_EDGES / 4 + t];
            sx[0] = s4.x; sx[1] = s4.y; sx[2] = s4.z; sx[3] = s4.w;
            dx[0] = d4.x; dx[1] = d4.y; dx[2] = d4.z; dx[3] = d4.w;
        }
#pragma unroll
        for (int j = 0; j < 4; j++) {
            float v = g_asrc[sx[j]] + g_adst[dx[j]];
            float lv = (v > 0.f) ? v : NEG_SLOPE * v;
            float ev = __expf(lv);
            int pos = atomicAdd(&g_cursor[dx[j]], 1);
            g_csr[pos] = pack_edge(sx[j], ev);
        }
    } else {
        int node = t - N_EDGES / 4;   // self loop
        if (node < N_NODES) {
            float v = g_asrc[node] + g_adst[node];
            float lv = (v > 0.f) ? v : NEG_SLOPE * v;
            float ev = __expf(lv);
            int pos = atomicAdd(&g_cursor[node], 1);
            g_csr[pos] = pack_edge(node, ev);
        }
    }
}

// ---------------- K5: fused aggregate + head (warp per node, no max pass) ----
__global__ __launch_bounds__(256) void k_agg(const float* __restrict__ bias,
                                             const float* __restrict__ wlin,
                                             const float* __restrict__ blin,
                                             float* __restrict__ y) {
    int node = blockIdx.x * 8 + (threadIdx.x >> 5);
    int lane = threadIdx.x & 31;
    if (node >= N_NODES) return;

    int beg = g_row_start[node];
    int end = g_row_start[node + 1];

    const float2* h2 = (const float2*)g_h;
    float2 acc = make_float2(0.f, 0.f);
    float s = 0.f;
    for (int base = beg; base < end; base += 32) {
        int i = base + lane;
        float ex = 0.f;
        int sid = 0;
        if (i < end) {
            long long p = g_csr[i];
            sid = (int)p;
            ex  = __int_as_float((int)(p >> 32));
        }
        s += ex;
        int cnt = min(32, end - base);
        for (int j = 0; j < cnt; j++) {
            float w = __shfl_sync(0xffffffffu, ex, j);
            int sj  = __shfl_sync(0xffffffffu, sid, j);
            float2 hv = h2[(size_t)sj * 32 + lane];
            acc.x += w * hv.x;
            acc.y += w * hv.y;
        }
    }
#pragma unroll
    for (int off = 16; off > 0; off >>= 1)
        s += __shfl_xor_sync(0xffffffffu, s, off);

    float inv = __frcp_rn(s);
    float o0 = fmaxf(acc.x * inv + bias[2 * lane], 0.f);
    float o1 = fmaxf(acc.y * inv + bias[2 * lane + 1], 0.f);
    float p = o0 * wlin[2 * lane] + o1 * wlin[2 * lane + 1];
#pragma unroll
    for (int off = 16; off > 0; off >>= 1)
        p += __shfl_xor_sync(0xffffffffu, p, off);
    if (lane == 0) {
        float t = p + blin[0];
        y[node] = __frcp_rn(1.f + __expf(-t));
    }
}

// ---------------- launch ----------------
extern "C" void kernel_launch(void* const* d_in, const int* in_sizes, int n_in,
                              void* d_out, int out_size) {
    const float* x       = (const float*)d_in[0];
    const void*  ei      = d_in[1];
    const float* W       = (const float*)d_in[2];
    const float* att_src = (const float*)d_in[3];
    const float* att_dst = (const float*)d_in[4];
    const float* bias    = (const float*)d_in[5];
    const float* wlin    = (const float*)d_in[6];
    const float* blin    = (const float*)d_in[7];
    float*       y       = (float*)d_out;

    k_init<<<(N_NODES + 255) / 256, 256>>>(ei);
    k_gemm<<<(N_NODES + GN - 1) / GN, 256>>>(x, W, att_src, att_dst);
    k_count<<<(N_EDGES / 4 + 255) / 256, 256>>>(ei);
    k_scan<<<SCAN_NBLK, 1024>>>();
    k_scatter<<<(N_EDGES / 4 + N_NODES + 255) / 256, 256>>>(ei);
    k_agg<<<(N_NODES + 7) / 8, 256>>>(bias, wlin, blin, y);
}